// round 2
// baseline (speedup 1.0000x reference)
#include <cuda_runtime.h>
#include <cuda_bf16.h>
#include <mma.h>

using namespace nvcuda;

#define NN 50000
#define NPAD 50048            // multiple of 64
#define NE 800000
#define NG 500
#define HD 128

// ---------------- static device scratch (allocation-free rule) ----------------
__device__ float d_h0[(size_t)NPAD * 128];
__device__ float d_h1[(size_t)NPAD * 128];
__device__ float d_G[(size_t)NPAD * 512];                  // [Af|Bf|As|Bs] per node
__device__ __nv_bfloat16 d_E[(size_t)NE * 768];            // per-edge RBF proj, 3 layers x (f,s) x 128
__device__ int d_cnt[NN];
__device__ int d_off[NN + 1];
__device__ int d_cur[NN];
__device__ int d_csr_src[NE];
__device__ int d_csr_eid[NE];
__device__ float d_pool[NG * HD];
__device__ float d_cntf[NG];
__device__ float d_Wcat[3 * 128 * 512];
__device__ float d_bcat[3 * 512];
__device__ float d_Wecat[32 * 768];

// ---------------- fast math ----------------
__device__ __forceinline__ float ex2f(float x) { float r; asm("ex2.approx.f32 %0, %1;" : "=f"(r) : "f"(x)); return r; }
__device__ __forceinline__ float lg2f(float x) { float r; asm("lg2.approx.f32 %0, %1;" : "=f"(r) : "f"(x)); return r; }
__device__ __forceinline__ float rcpf(float x) { float r; asm("rcp.approx.f32 %0, %1;" : "=f"(r) : "f"(x)); return r; }
__device__ __forceinline__ float tf32r(float x) { float r; asm("cvt.rna.tf32.f32 %0, %1;" : "=f"(r) : "f"(x)); return r; }

#define LOG2E 1.4426950408889634f
#define LN2   0.6931471805599453f

__device__ __forceinline__ float msgf(float pf, float ps) {
    float sg = rcpf(1.0f + ex2f(-pf * LOG2E));
    float sp = LN2 * lg2f(1.0f + ex2f(ps * LOG2E));
    sp = (ps > 15.0f) ? ps : sp;
    return sg * sp;
}

// ---------------- misc kernels ----------------
__global__ void zero_stats() {
    int i = blockIdx.x * blockDim.x + threadIdx.x;
    if (i < NG * HD) d_pool[i] = 0.0f;
    if (i < NG) d_cntf[i] = 0.0f;
    if (i < NN) d_cnt[i] = 0;
}

__global__ void repack_kernel(const float* __restrict__ Wf1, const float* __restrict__ Ws1,
                              const float* __restrict__ Wf2, const float* __restrict__ Ws2,
                              const float* __restrict__ Wf3, const float* __restrict__ Ws3,
                              const float* __restrict__ bf1, const float* __restrict__ bs1,
                              const float* __restrict__ bf2, const float* __restrict__ bs2,
                              const float* __restrict__ bf3, const float* __restrict__ bs3) {
    int idx = blockIdx.x * blockDim.x + threadIdx.x;
    const float* Wf[3] = {Wf1, Wf2, Wf3};
    const float* Ws[3] = {Ws1, Ws2, Ws3};
    if (idx < 3 * 128 * 512) {
        int l = idx / 65536;
        int rem = idx - l * 65536;
        int k = rem >> 9;
        int c = rem & 511;
        int g = c >> 7;            // 0 Af, 1 Bf, 2 As, 3 Bs
        int c0 = c & 127;
        float v;
        if (g == 0)      v = Wf[l][k * 128 + c0];
        else if (g == 1) v = Wf[l][(128 + k) * 128 + c0];
        else if (g == 2) v = Ws[l][k * 128 + c0];
        else             v = Ws[l][(128 + k) * 128 + c0];
        d_Wcat[idx] = v;
        return;
    }
    int idx2 = idx - 3 * 128 * 512;
    if (idx2 < 32 * 768) {
        int r = idx2 / 768;
        int c = idx2 - r * 768;
        int l = c >> 8;            // layer
        int g = (c >> 7) & 1;      // 0 f, 1 s
        int c0 = c & 127;
        d_Wecat[idx2] = (g == 0 ? Wf[l] : Ws[l])[(256 + r) * 128 + c0];
        return;
    }
    int idx3 = idx2 - 32 * 768;
    if (idx3 < 3 * 512) {
        int l = idx3 / 512;
        int c = idx3 - l * 512;
        int g = c >> 7;
        int c0 = c & 127;
        const float* bfp[3] = {bf1, bf2, bf3};
        const float* bsp[3] = {bs1, bs2, bs3};
        float v = (g == 0) ? bfp[l][c0] : ((g == 2) ? bsp[l][c0] : 0.0f);
        d_bcat[idx3] = v;
    }
}

__global__ void count_kernel(const int* __restrict__ dst) {
    int e = blockIdx.x * blockDim.x + threadIdx.x;
    if (e < NE) atomicAdd(&d_cnt[dst[e]], 1);
}

__global__ void scan_kernel() {
    __shared__ int wsum[32];
    __shared__ int sbase;
    int lane = threadIdx.x & 31, wid = threadIdx.x >> 5;
    if (threadIdx.x == 0) sbase = 0;
    __syncthreads();
    for (int start = 0; start < NN; start += 1024) {
        int i = start + threadIdx.x;
        int v = (i < NN) ? d_cnt[i] : 0;
        int x = v;
        #pragma unroll
        for (int o = 1; o < 32; o <<= 1) {
            int t = __shfl_up_sync(0xffffffffu, x, o);
            if (lane >= o) x += t;
        }
        if (lane == 31) wsum[wid] = x;
        __syncthreads();
        if (wid == 0) {
            int t2 = wsum[lane];
            #pragma unroll
            for (int o = 1; o < 32; o <<= 1) {
                int t = __shfl_up_sync(0xffffffffu, t2, o);
                if (lane >= o) t2 += t;
            }
            wsum[lane] = t2;
        }
        __syncthreads();
        int warpoff = (wid == 0) ? 0 : wsum[wid - 1];
        int excl = sbase + warpoff + (x - v);
        if (i < NN) { d_off[i] = excl; d_cur[i] = excl; }
        __syncthreads();
        if (threadIdx.x == 0) sbase += wsum[31];
        __syncthreads();
    }
    if (threadIdx.x == 0) d_off[NN] = sbase;
}

__global__ void scatter_kernel(const int* __restrict__ src, const int* __restrict__ dst) {
    int e = blockIdx.x * blockDim.x + threadIdx.x;
    if (e < NE) {
        int d = dst[e];
        int p = atomicAdd(&d_cur[d], 1);
        d_csr_src[p] = src[e];
        d_csr_eid[p] = e;
    }
}

__global__ void embed_kernel(const int* __restrict__ x, const float* __restrict__ emb) {
    int idx = blockIdx.x * blockDim.x + threadIdx.x;
    if (idx >= NN * 32) return;
    int n = idx >> 5, c4 = idx & 31;
    float4 v = ((const float4*)(emb + (size_t)x[n] * 128))[c4];
    ((float4*)(d_h0 + (size_t)n * 128))[c4] = v;
}

// ---------------- tf32 wmma GEMM: C[M,*] = A[M,K] @ B[K,ldb-chunk] (+bias) ----------------
// Block: 64(M) x 64(N) tile, 256 threads = 8 warps in 2x4. OBF=1 -> bf16 output.
template <int K, int OBF>
__global__ void __launch_bounds__(256)
gemm_tf32(const float* __restrict__ A, const float* __restrict__ B,
          const float* __restrict__ bias, void* __restrict__ Cv,
          int ldb, int ldc) {
    extern __shared__ float sm[];
    float (*As)[K + 4] = (float (*)[K + 4])sm;
    float (*Bs)[68]    = (float (*)[68])(sm + 64 * (K + 4));
    float (*Us)[68]    = (float (*)[68])(sm + 64 * (K + 4) + K * 68);

    int tid = threadIdx.x;
    size_t rowBase = (size_t)blockIdx.x * 64;
    int colBase = blockIdx.y * 64;

    constexpr int K4 = K / 4;
    for (int i = tid; i < 64 * K4; i += 256) {
        int r = i / K4, c = (i - r * K4) * 4;
        float4 v = *(const float4*)&A[(rowBase + r) * K + c];
        v.x = tf32r(v.x); v.y = tf32r(v.y); v.z = tf32r(v.z); v.w = tf32r(v.w);
        *(float4*)&As[r][c] = v;
    }
    for (int i = tid; i < K * 16; i += 256) {
        int r = i / 16, c = (i - r * 16) * 4;
        float4 v = *(const float4*)&B[(size_t)r * ldb + colBase + c];
        v.x = tf32r(v.x); v.y = tf32r(v.y); v.z = tf32r(v.z); v.w = tf32r(v.w);
        *(float4*)&Bs[r][c] = v;
    }
    __syncthreads();

    int warp = tid >> 5;
    int wm = warp >> 2, wn = warp & 3;   // wm: 0..1 (32 rows each), wn: 0..3 (16 cols each)

    wmma::fragment<wmma::accumulator, 16, 16, 8, float> c0, c1;
    wmma::fill_fragment(c0, 0.0f);
    wmma::fill_fragment(c1, 0.0f);

    #pragma unroll
    for (int k0 = 0; k0 < K; k0 += 8) {
        wmma::fragment<wmma::matrix_a, 16, 16, 8, wmma::precision::tf32, wmma::row_major> a0, a1;
        wmma::fragment<wmma::matrix_b, 16, 16, 8, wmma::precision::tf32, wmma::row_major> b;
        wmma::load_matrix_sync(a0, &As[wm * 32][k0], K + 4);
        wmma::load_matrix_sync(a1, &As[wm * 32 + 16][k0], K + 4);
        wmma::load_matrix_sync(b, &Bs[k0][wn * 16], 68);
        wmma::mma_sync(c0, a0, b, c0);
        wmma::mma_sync(c1, a1, b, c1);
    }
    wmma::store_matrix_sync(&Us[wm * 32][wn * 16], c0, 68, wmma::mem_row_major);
    wmma::store_matrix_sync(&Us[wm * 32 + 16][wn * 16], c1, 68, wmma::mem_row_major);
    __syncthreads();

    for (int i = tid; i < 4096; i += 256) {
        int r = i >> 6, c = i & 63;
        float v = Us[r][c];
        if (bias) v += bias[colBase + c];
        if (OBF) ((__nv_bfloat16*)Cv)[(rowBase + r) * (size_t)ldc + colBase + c] = __float2bfloat16(v);
        else     ((float*)Cv)[(rowBase + r) * (size_t)ldc + colBase + c] = v;
    }
}

// ---------------- edge kernel: one warp per dst node, atomic-free ----------------
__global__ void __launch_bounds__(256) edge_kernel(int layer) {
    int n = blockIdx.x * 8 + (threadIdx.x >> 5);
    if (n >= NN) return;
    int l = threadIdx.x & 31;
    const float* hin  = (layer == 1) ? d_h1 : d_h0;
    float*       hout = (layer == 1) ? d_h0 : d_h1;

    const float4* Gn = (const float4*)(d_G + (size_t)n * 512);
    float4 af  = Gn[l];        // f, dst part (bias folded)
    float4 as4 = Gn[64 + l];   // s, dst part (bias folded)
    float4 acc = make_float4(0.f, 0.f, 0.f, 0.f);

    int beg = d_off[n], end = d_off[n + 1];
    for (int p = beg; p < end; ++p) {
        int s = d_csr_src[p];
        int e = d_csr_eid[p];
        const float4* Gs = (const float4*)(d_G + (size_t)s * 512);
        float4 bf4 = Gs[32 + l];   // f, src part
        float4 bs4 = Gs[96 + l];   // s, src part
        const __nv_bfloat16* Eb = d_E + (size_t)e * 768 + layer * 256;
        uint2 qf = *(const uint2*)(Eb + 4 * l);
        uint2 qs = *(const uint2*)(Eb + 128 + 4 * l);
        float2 ef0 = __bfloat1622float2(*(__nv_bfloat162*)&qf.x);
        float2 ef1 = __bfloat1622float2(*(__nv_bfloat162*)&qf.y);
        float2 es0 = __bfloat1622float2(*(__nv_bfloat162*)&qs.x);
        float2 es1 = __bfloat1622float2(*(__nv_bfloat162*)&qs.y);
        acc.x += msgf(af.x + bf4.x + ef0.x, as4.x + bs4.x + es0.x);
        acc.y += msgf(af.y + bf4.y + ef0.y, as4.y + bs4.y + es0.y);
        acc.z += msgf(af.z + bf4.z + ef1.x, as4.z + bs4.z + es1.x);
        acc.w += msgf(af.w + bf4.w + ef1.y, as4.w + bs4.w + es1.y);
    }
    float4 h = ((const float4*)(hin + (size_t)n * 128))[l];
    h.x = fmaxf(h.x + acc.x, 0.f);
    h.y = fmaxf(h.y + acc.y, 0.f);
    h.z = fmaxf(h.z + acc.z, 0.f);
    h.w = fmaxf(h.w + acc.w, 0.f);
    ((float4*)(hout + (size_t)n * 128))[l] = h;
}

// ---------------- pooling: run-length segmented (batch is sorted) ----------------
__global__ void pool_kernel(const float* __restrict__ h, const int* __restrict__ batch) {
    int t = threadIdx.x;  // channel 0..127
    int per = (NN + gridDim.x - 1) / gridDim.x;
    int n0 = blockIdx.x * per;
    int n1 = n0 + per; if (n1 > NN) n1 = NN;
    if (n0 >= n1) return;
    int g = batch[n0];
    float acc = 0.f, cnt = 0.f;
    for (int n = n0; n < n1; ++n) {
        int gn = batch[n];
        if (gn != g) {
            atomicAdd(&d_pool[g * 128 + t], acc);
            if (t == 0) atomicAdd(&d_cntf[g], cnt);
            acc = 0.f; cnt = 0.f; g = gn;
        }
        acc += h[(size_t)n * 128 + t];
        cnt += 1.f;
    }
    atomicAdd(&d_pool[g * 128 + t], acc);
    if (t == 0) atomicAdd(&d_cntf[g], cnt);
}

__global__ void final_kernel(const float* __restrict__ Wlin, const float* __restrict__ blin,
                             float* __restrict__ out) {
    __shared__ float pm[128];
    int gph = blockIdx.x, t = threadIdx.x;
    float inv = 1.0f / fmaxf(d_cntf[gph], 1.0f);
    pm[t] = d_pool[gph * 128 + t] * inv;
    __syncthreads();
    float s = blin[t];
    #pragma unroll 8
    for (int k = 0; k < 128; ++k) s += pm[k] * Wlin[k * 128 + t];
    out[gph * 128 + t] = s;
}

// ---------------- host ----------------
extern "C" void kernel_launch(void* const* d_in, const int* in_sizes, int n_in,
                              void* d_out, int out_size) {
    const int*   x     = (const int*)d_in[0];
    const int*   ei    = (const int*)d_in[1];
    const float* ea    = (const float*)d_in[2];
    const int*   batch = (const int*)d_in[3];
    const float* emb   = (const float*)d_in[4];
    const float* Wf1 = (const float*)d_in[5],  *bf1 = (const float*)d_in[6];
    const float* Ws1 = (const float*)d_in[7],  *bs1 = (const float*)d_in[8];
    const float* Wf2 = (const float*)d_in[9],  *bf2 = (const float*)d_in[10];
    const float* Ws2 = (const float*)d_in[11], *bs2 = (const float*)d_in[12];
    const float* Wf3 = (const float*)d_in[13], *bf3 = (const float*)d_in[14];
    const float* Ws3 = (const float*)d_in[15], *bs3 = (const float*)d_in[16];
    const float* Wlin = (const float*)d_in[17], *blin = (const float*)d_in[18];
    float* out = (float*)d_out;

    const int* src = ei;
    const int* dst = ei + NE;

    const int SMEM_NODE = (64 * 132 + 128 * 68 + 64 * 68) * 4;  // 86016
    const int SMEM_E    = (64 * 36  + 32 * 68  + 64 * 68) * 4;  // 35328
    cudaFuncSetAttribute(gemm_tf32<128, 0>, cudaFuncAttributeMaxDynamicSharedMemorySize, SMEM_NODE);

    void *p_h0, *p_h1, *p_G, *p_E, *p_Wcat, *p_bcat, *p_Wecat;
    cudaGetSymbolAddress(&p_h0, d_h0);
    cudaGetSymbolAddress(&p_h1, d_h1);
    cudaGetSymbolAddress(&p_G, d_G);
    cudaGetSymbolAddress(&p_E, d_E);
    cudaGetSymbolAddress(&p_Wcat, d_Wcat);
    cudaGetSymbolAddress(&p_bcat, d_bcat);
    cudaGetSymbolAddress(&p_Wecat, d_Wecat);

    zero_stats<<<250, 256>>>();
    repack_kernel<<<(3 * 128 * 512 + 32 * 768 + 3 * 512 + 255) / 256, 256>>>(
        Wf1, Ws1, Wf2, Ws2, Wf3, Ws3, bf1, bs1, bf2, bs2, bf3, bs3);
    count_kernel<<<(NE + 255) / 256, 256>>>(dst);
    scan_kernel<<<1, 1024>>>();
    scatter_kernel<<<(NE + 255) / 256, 256>>>(src, dst);
    embed_kernel<<<(NN * 32 + 255) / 256, 256>>>(x, emb);

    // E = edge_attr @ Wecat -> bf16 [NE, 768]
    {
        dim3 grid(NE / 64, 12);
        gemm_tf32<32, 1><<<grid, 256, SMEM_E>>>(ea, (const float*)p_Wecat, nullptr, p_E, 768, 768);
    }

    float* hbufs[4] = {(float*)p_h0, (float*)p_h1, (float*)p_h0, (float*)p_h1};
    for (int l = 0; l < 3; ++l) {
        dim3 grid(NPAD / 64, 8);
        gemm_tf32<128, 0><<<grid, 256, SMEM_NODE>>>(
            hbufs[l], (const float*)p_Wcat + l * 65536,
            (const float*)p_bcat + l * 512, p_G, 512, 512);
        edge_kernel<<<(NN + 7) / 8, 256>>>(l);
    }

    pool_kernel<<<512, 128>>>((const float*)p_h1, batch);
    final_kernel<<<NG, 128>>>(Wlin, blin, out);
}

// round 5
// speedup vs baseline: 1.0454x; 1.0454x over previous
#include <cuda_runtime.h>
#include <cuda_bf16.h>
#include <mma.h>

using namespace nvcuda;

#define NN 50000
#define NPAD 50048            // multiple of 64
#define NE 800000
#define NG 500
#define HD 128
#define NB_SCAN 196           // ceil(50000/256)

// ---------------- static device scratch (allocation-free rule) ----------------
__device__ float d_h0[(size_t)NPAD * 128];
__device__ float d_h1[(size_t)NPAD * 128];
__device__ float d_G[(size_t)NPAD * 512];                  // [Af|Bf|As|Bs] per node
__device__ __nv_bfloat16 d_E[(size_t)NE * 768];            // per-edge, 3 layers x 256, lane-interleaved f/s
__device__ int d_cnt[NN];
__device__ int d_off[NN + 1];
__device__ int d_cur[NN];
__device__ int2 d_csr[NE];                                  // (src, eid)
__device__ int d_bsum[256];
__device__ float d_pool[NG * HD];
__device__ float d_cntf[NG];
__device__ float d_Wcat[3 * 128 * 512];
__device__ float d_bcat[3 * 512];
__device__ float d_Wecat[32 * 768];

// ---------------- fast math ----------------
__device__ __forceinline__ float ex2f(float x) { float r; asm("ex2.approx.f32 %0, %1;" : "=f"(r) : "f"(x)); return r; }
__device__ __forceinline__ float lg2f(float x) { float r; asm("lg2.approx.f32 %0, %1;" : "=f"(r) : "f"(x)); return r; }
__device__ __forceinline__ float tanhf_(float x){ float r; asm("tanh.approx.f32 %0, %1;" : "=f"(r) : "f"(x)); return r; }
__device__ __forceinline__ float tf32r(float x) { float r; asm("cvt.rna.tf32.f32 %0, %1;" : "=f"(r) : "f"(x)); return r; }

#define LOG2E 1.4426950408889634f
#define LN2   0.6931471805599453f

__device__ __forceinline__ float msgf(float pf, float ps) {
    float sg = fmaf(0.5f, tanhf_(0.5f * pf), 0.5f);          // sigmoid, 1 MUFU
    float sp = LN2 * lg2f(1.0f + ex2f(ps * LOG2E));          // softplus, 2 MUFU
    sp = (ps > 15.0f) ? ps : sp;
    return sg * sp;
}

// ---------------- misc kernels ----------------
__global__ void zero_stats() {
    int i = blockIdx.x * blockDim.x + threadIdx.x;
    if (i < NG * HD) d_pool[i] = 0.0f;
    if (i < NG) d_cntf[i] = 0.0f;
    if (i < NN) d_cnt[i] = 0;
}

__global__ void repack_kernel(const float* __restrict__ Wf1, const float* __restrict__ Ws1,
                              const float* __restrict__ Wf2, const float* __restrict__ Ws2,
                              const float* __restrict__ Wf3, const float* __restrict__ Ws3,
                              const float* __restrict__ bf1, const float* __restrict__ bs1,
                              const float* __restrict__ bf2, const float* __restrict__ bs2,
                              const float* __restrict__ bf3, const float* __restrict__ bs3) {
    int idx = blockIdx.x * blockDim.x + threadIdx.x;
    const float* Wf[3] = {Wf1, Wf2, Wf3};
    const float* Ws[3] = {Ws1, Ws2, Ws3};
    if (idx < 3 * 128 * 512) {
        int l = idx / 65536;
        int rem = idx - l * 65536;
        int k = rem >> 9;
        int c = rem & 511;
        int g = c >> 7;            // 0 Af, 1 Bf, 2 As, 3 Bs
        int c0 = c & 127;
        float v;
        if (g == 0)      v = Wf[l][k * 128 + c0];
        else if (g == 1) v = Wf[l][(128 + k) * 128 + c0];
        else if (g == 2) v = Ws[l][k * 128 + c0];
        else             v = Ws[l][(128 + k) * 128 + c0];
        d_Wcat[idx] = v;
        return;
    }
    int idx2 = idx - 3 * 128 * 512;
    if (idx2 < 32 * 768) {
        // lane-interleaved layout: within each layer's 256 cols,
        // cols 8*li .. 8*li+3 = f channels 4li..4li+3, 8*li+4 .. 8*li+7 = s channels 4li..4li+3
        int r = idx2 / 768;
        int c = idx2 - r * 768;
        int l = c >> 8;            // layer
        int w = c & 255;
        int li = w >> 3;           // lane 0..31
        int q = w & 7;
        int g = q >> 2;            // 0 f, 1 s
        int c0 = 4 * li + (q & 3);
        d_Wecat[idx2] = (g == 0 ? Wf[l] : Ws[l])[(256 + r) * 128 + c0];
        return;
    }
    int idx3 = idx2 - 32 * 768;
    if (idx3 < 3 * 512) {
        int l = idx3 / 512;
        int c = idx3 - l * 512;
        int g = c >> 7;
        int c0 = c & 127;
        const float* bfp[3] = {bf1, bf2, bf3};
        const float* bsp[3] = {bs1, bs2, bs3};
        float v = (g == 0) ? bfp[l][c0] : ((g == 2) ? bsp[l][c0] : 0.0f);
        d_bcat[idx3] = v;
    }
}

__global__ void count_kernel(const int* __restrict__ dst) {
    int e = blockIdx.x * blockDim.x + threadIdx.x;
    if (e < NE) atomicAdd(&d_cnt[dst[e]], 1);
}

// ---- hierarchical scan: block-local, top, add ----
__device__ __forceinline__ int block_scan_incl(int v, int* wsum, int lane, int wid) {
    int x = v;
    #pragma unroll
    for (int o = 1; o < 32; o <<= 1) {
        int t = __shfl_up_sync(0xffffffffu, x, o);
        if (lane >= o) x += t;
    }
    if (lane == 31) wsum[wid] = x;
    __syncthreads();
    if (wid == 0) {
        int t2 = (lane < 8) ? wsum[lane] : 0;
        #pragma unroll
        for (int o = 1; o < 8; o <<= 1) {
            int t = __shfl_up_sync(0xffffffffu, t2, o);
            if (lane >= o) t2 += t;
        }
        if (lane < 8) wsum[lane] = t2;
    }
    __syncthreads();
    return x + (wid ? wsum[wid - 1] : 0);
}

__global__ void scan_blocks() {
    __shared__ int wsum[8];
    int lane = threadIdx.x & 31, wid = threadIdx.x >> 5;
    int i = blockIdx.x * 256 + threadIdx.x;
    int v = (i < NN) ? d_cnt[i] : 0;
    int incl = block_scan_incl(v, wsum, lane, wid);
    if (i < NN) d_off[i] = incl - v;                 // exclusive within block
    if (threadIdx.x == 255) d_bsum[blockIdx.x] = incl;
}

__global__ void scan_top() {
    __shared__ int wsum[8];
    int lane = threadIdx.x & 31, wid = threadIdx.x >> 5;
    int t = threadIdx.x;
    int v = (t < NB_SCAN) ? d_bsum[t] : 0;
    int incl = block_scan_incl(v, wsum, lane, wid);
    if (t < NB_SCAN) d_bsum[t] = incl - v;           // exclusive block bases
}

__global__ void scan_add() {
    int i = blockIdx.x * 256 + threadIdx.x;
    if (i < NN) {
        int o = d_off[i] + d_bsum[blockIdx.x];
        d_off[i] = o;
        d_cur[i] = o;
    }
    if (i == 0) d_off[NN] = NE;
}

__global__ void scatter_kernel(const int* __restrict__ src, const int* __restrict__ dst) {
    int e = blockIdx.x * blockDim.x + threadIdx.x;
    if (e < NE) {
        int d = dst[e];
        int p = atomicAdd(&d_cur[d], 1);
        d_csr[p] = make_int2(src[e], e);
    }
}

__global__ void embed_kernel(const int* __restrict__ x, const float* __restrict__ emb) {
    int idx = blockIdx.x * blockDim.x + threadIdx.x;
    if (idx >= NN * 32) return;
    int n = idx >> 5, c4 = idx & 31;
    float4 v = ((const float4*)(emb + (size_t)x[n] * 128))[c4];
    ((float4*)(d_h0 + (size_t)n * 128))[c4] = v;
}

// ---------------- tf32 wmma GEMM: C[M,*] = A[M,K] @ B[K,ldb-chunk] (+bias) ----------------
template <int K, int OBF>
__global__ void __launch_bounds__(256)
gemm_tf32(const float* __restrict__ A, const float* __restrict__ B,
          const float* __restrict__ bias, void* __restrict__ Cv,
          int ldb, int ldc) {
    extern __shared__ float sm[];
    float (*As)[K + 4] = (float (*)[K + 4])sm;
    float (*Bs)[68]    = (float (*)[68])(sm + 64 * (K + 4));
    float (*Us)[68]    = (float (*)[68])(sm + 64 * (K + 4) + K * 68);

    int tid = threadIdx.x;
    size_t rowBase = (size_t)blockIdx.x * 64;
    int colBase = blockIdx.y * 64;

    constexpr int K4 = K / 4;
    for (int i = tid; i < 64 * K4; i += 256) {
        int r = i / K4, c = (i - r * K4) * 4;
        float4 v = *(const float4*)&A[(rowBase + r) * K + c];
        v.x = tf32r(v.x); v.y = tf32r(v.y); v.z = tf32r(v.z); v.w = tf32r(v.w);
        *(float4*)&As[r][c] = v;
    }
    for (int i = tid; i < K * 16; i += 256) {
        int r = i / 16, c = (i - r * 16) * 4;
        float4 v = *(const float4*)&B[(size_t)r * ldb + colBase + c];
        v.x = tf32r(v.x); v.y = tf32r(v.y); v.z = tf32r(v.z); v.w = tf32r(v.w);
        *(float4*)&Bs[r][c] = v;
    }
    __syncthreads();

    int warp = tid >> 5;
    int wm = warp >> 2, wn = warp & 3;

    wmma::fragment<wmma::accumulator, 16, 16, 8, float> c0, c1;
    wmma::fill_fragment(c0, 0.0f);
    wmma::fill_fragment(c1, 0.0f);

    #pragma unroll
    for (int k0 = 0; k0 < K; k0 += 8) {
        wmma::fragment<wmma::matrix_a, 16, 16, 8, wmma::precision::tf32, wmma::row_major> a0, a1;
        wmma::fragment<wmma::matrix_b, 16, 16, 8, wmma::precision::tf32, wmma::row_major> b;
        wmma::load_matrix_sync(a0, &As[wm * 32][k0], K + 4);
        wmma::load_matrix_sync(a1, &As[wm * 32 + 16][k0], K + 4);
        wmma::load_matrix_sync(b, &Bs[k0][wn * 16], 68);
        wmma::mma_sync(c0, a0, b, c0);
        wmma::mma_sync(c1, a1, b, c1);
    }
    wmma::store_matrix_sync(&Us[wm * 32][wn * 16], c0, 68, wmma::mem_row_major);
    wmma::store_matrix_sync(&Us[wm * 32 + 16][wn * 16], c1, 68, wmma::mem_row_major);
    __syncthreads();

    if (OBF) {
        // bf16 output, 8 elems per STG.128
        __nv_bfloat16* C = (__nv_bfloat16*)Cv;
        for (int i = tid; i < 512; i += 256) {
            int r = i >> 3, c = (i & 7) << 3;
            const float* u = &Us[r][c];
            float4 v0 = *(const float4*)&u[0];
            float4 v1 = *(const float4*)&u[4];
            __nv_bfloat162 p0 = __float22bfloat162_rn(make_float2(v0.x, v0.y));
            __nv_bfloat162 p1 = __float22bfloat162_rn(make_float2(v0.z, v0.w));
            __nv_bfloat162 p2 = __float22bfloat162_rn(make_float2(v1.x, v1.y));
            __nv_bfloat162 p3 = __float22bfloat162_rn(make_float2(v1.z, v1.w));
            uint4 pk;
            pk.x = *(unsigned*)&p0; pk.y = *(unsigned*)&p1;
            pk.z = *(unsigned*)&p2; pk.w = *(unsigned*)&p3;
            *(uint4*)&C[(rowBase + r) * (size_t)ldc + colBase + c] = pk;
        }
    } else {
        float* C = (float*)Cv;
        for (int i = tid; i < 1024; i += 256) {
            int r = i >> 4, c = (i & 15) << 2;
            float4 v = *(const float4*)&Us[r][c];
            if (bias) {
                float4 b4 = *(const float4*)&bias[colBase + c];
                v.x += b4.x; v.y += b4.y; v.z += b4.z; v.w += b4.w;
            }
            *(float4*)&C[(rowBase + r) * (size_t)ldc + colBase + c] = v;
        }
    }
}

// ---------------- edge kernel: one warp per dst node, atomic-free ----------------
__global__ void __launch_bounds__(256) edge_kernel(int layer) {
    int n = blockIdx.x * 8 + (threadIdx.x >> 5);
    if (n >= NN) return;
    int l = threadIdx.x & 31;
    const float* hin  = (layer == 1) ? d_h1 : d_h0;
    float*       hout = (layer == 1) ? d_h0 : d_h1;

    const float4* Gn = (const float4*)(d_G + (size_t)n * 512);
    float4 af  = Gn[l];
    float4 as4 = Gn[64 + l];
    float4 acc = make_float4(0.f, 0.f, 0.f, 0.f);

    int beg = d_off[n], end = d_off[n + 1];
    int p = beg;
    for (; p + 2 <= end; p += 2) {
        int2 e0 = d_csr[p];
        int2 e1 = d_csr[p + 1];
        const float4* G0 = (const float4*)(d_G + (size_t)e0.x * 512);
        const float4* G1 = (const float4*)(d_G + (size_t)e1.x * 512);
        float4 bf0 = G0[32 + l], bs0 = G0[96 + l];
        float4 bf1_ = G1[32 + l], bs1_ = G1[96 + l];
        // single 16B load per edge: [f0 f1 | f2 f3 | s0 s1 | s2 s3] bf16 pairs for lane l
        uint4 q0 = *(const uint4*)(d_E + (size_t)e0.y * 768 + layer * 256 + 8 * l);
        uint4 q1 = *(const uint4*)(d_E + (size_t)e1.y * 768 + layer * 256 + 8 * l);

        {
            float2 ef0 = __bfloat1622float2(*(__nv_bfloat162*)&q0.x);
            float2 ef1 = __bfloat1622float2(*(__nv_bfloat162*)&q0.y);
            float2 es0 = __bfloat1622float2(*(__nv_bfloat162*)&q0.z);
            float2 es1 = __bfloat1622float2(*(__nv_bfloat162*)&q0.w);
            acc.x += msgf(af.x + bf0.x + ef0.x, as4.x + bs0.x + es0.x);
            acc.y += msgf(af.y + bf0.y + ef0.y, as4.y + bs0.y + es0.y);
            acc.z += msgf(af.z + bf0.z + ef1.x, as4.z + bs0.z + es1.x);
            acc.w += msgf(af.w + bf0.w + ef1.y, as4.w + bs0.w + es1.y);
        }
        {
            float2 ef0 = __bfloat1622float2(*(__nv_bfloat162*)&q1.x);
            float2 ef1 = __bfloat1622float2(*(__nv_bfloat162*)&q1.y);
            float2 es0 = __bfloat1622float2(*(__nv_bfloat162*)&q1.z);
            float2 es1 = __bfloat1622float2(*(__nv_bfloat162*)&q1.w);
            acc.x += msgf(af.x + bf1_.x + ef0.x, as4.x + bs1_.x + es0.x);
            acc.y += msgf(af.y + bf1_.y + ef0.y, as4.y + bs1_.y + es0.y);
            acc.z += msgf(af.z + bf1_.z + ef1.x, as4.z + bs1_.z + es1.x);
            acc.w += msgf(af.w + bf1_.w + ef1.y, as4.w + bs1_.w + es1.y);
        }
    }
    if (p < end) {
        int2 e0 = d_csr[p];
        const float4* G0 = (const float4*)(d_G + (size_t)e0.x * 512);
        float4 bf0 = G0[32 + l], bs0 = G0[96 + l];
        uint4 q0 = *(const uint4*)(d_E + (size_t)e0.y * 768 + layer * 256 + 8 * l);
        float2 ef0 = __bfloat1622float2(*(__nv_bfloat162*)&q0.x);
        float2 ef1 = __bfloat1622float2(*(__nv_bfloat162*)&q0.y);
        float2 es0 = __bfloat1622float2(*(__nv_bfloat162*)&q0.z);
        float2 es1 = __bfloat1622float2(*(__nv_bfloat162*)&q0.w);
        acc.x += msgf(af.x + bf0.x + ef0.x, as4.x + bs0.x + es0.x);
        acc.y += msgf(af.y + bf0.y + ef0.y, as4.y + bs0.y + es0.y);
        acc.z += msgf(af.z + bf0.z + ef1.x, as4.z + bs0.z + es1.x);
        acc.w += msgf(af.w + bf0.w + ef1.y, as4.w + bs0.w + es1.y);
    }
    float4 h = ((const float4*)(hin + (size_t)n * 128))[l];
    h.x = fmaxf(h.x + acc.x, 0.f);
    h.y = fmaxf(h.y + acc.y, 0.f);
    h.z = fmaxf(h.z + acc.z, 0.f);
    h.w = fmaxf(h.w + acc.w, 0.f);
    ((float4*)(hout + (size_t)n * 128))[l] = h;
}

// ---------------- pooling ----------------
__global__ void pool_kernel(const float* __restrict__ h, const int* __restrict__ batch) {
    int t = threadIdx.x;
    int per = (NN + gridDim.x - 1) / gridDim.x;
    int n0 = blockIdx.x * per;
    int n1 = n0 + per; if (n1 > NN) n1 = NN;
    if (n0 >= n1) return;
    int g = batch[n0];
    float acc = 0.f, cnt = 0.f;
    for (int n = n0; n < n1; ++n) {
        int gn = batch[n];
        if (gn != g) {
            atomicAdd(&d_pool[g * 128 + t], acc);
            if (t == 0) atomicAdd(&d_cntf[g], cnt);
            acc = 0.f; cnt = 0.f; g = gn;
        }
        acc += h[(size_t)n * 128 + t];
        cnt += 1.f;
    }
    atomicAdd(&d_pool[g * 128 + t], acc);
    if (t == 0) atomicAdd(&d_cntf[g], cnt);
}

__global__ void final_kernel(const float* __restrict__ Wlin, const float* __restrict__ blin,
                             float* __restrict__ out) {
    __shared__ float pm[128];
    int gph = blockIdx.x, t = threadIdx.x;
    float inv = 1.0f / fmaxf(d_cntf[gph], 1.0f);
    pm[t] = d_pool[gph * 128 + t] * inv;
    __syncthreads();
    float s = blin[t];
    #pragma unroll 8
    for (int k = 0; k < 128; ++k) s += pm[k] * Wlin[k * 128 + t];
    out[gph * 128 + t] = s;
}

// ---------------- host ----------------
extern "C" void kernel_launch(void* const* d_in, const int* in_sizes, int n_in,
                              void* d_out, int out_size) {
    const int*   x     = (const int*)d_in[0];
    const int*   ei    = (const int*)d_in[1];
    const float* ea    = (const float*)d_in[2];
    const int*   batch = (const int*)d_in[3];
    const float* emb   = (const float*)d_in[4];
    const float* Wf1 = (const float*)d_in[5],  *bf1 = (const float*)d_in[6];
    const float* Ws1 = (const float*)d_in[7],  *bs1 = (const float*)d_in[8];
    const float* Wf2 = (const float*)d_in[9],  *bf2 = (const float*)d_in[10];
    const float* Ws2 = (const float*)d_in[11], *bs2 = (const float*)d_in[12];
    const float* Wf3 = (const float*)d_in[13], *bf3 = (const float*)d_in[14];
    const float* Ws3 = (const float*)d_in[15], *bs3 = (const float*)d_in[16];
    const float* Wlin = (const float*)d_in[17], *blin = (const float*)d_in[18];
    float* out = (float*)d_out;

    const int* src = ei;
    const int* dst = ei + NE;

    const int SMEM_NODE = (64 * 132 + 128 * 68 + 64 * 68) * 4;  // 86016
    const int SMEM_E    = (64 * 36  + 32 * 68  + 64 * 68) * 4;  // 35328
    cudaFuncSetAttribute(gemm_tf32<128, 0>, cudaFuncAttributeMaxDynamicSharedMemorySize, SMEM_NODE);

    void *p_h0, *p_h1, *p_G, *p_E, *p_Wcat, *p_bcat, *p_Wecat;
    cudaGetSymbolAddress(&p_h0, d_h0);
    cudaGetSymbolAddress(&p_h1, d_h1);
    cudaGetSymbolAddress(&p_G, d_G);
    cudaGetSymbolAddress(&p_E, d_E);
    cudaGetSymbolAddress(&p_Wcat, d_Wcat);
    cudaGetSymbolAddress(&p_bcat, d_bcat);
    cudaGetSymbolAddress(&p_Wecat, d_Wecat);

    zero_stats<<<250, 256>>>();
    repack_kernel<<<(3 * 128 * 512 + 32 * 768 + 3 * 512 + 255) / 256, 256>>>(
        Wf1, Ws1, Wf2, Ws2, Wf3, Ws3, bf1, bs1, bf2, bs2, bf3, bs3);
    count_kernel<<<(NE + 255) / 256, 256>>>(dst);
    scan_blocks<<<NB_SCAN, 256>>>();
    scan_top<<<1, 256>>>();
    scan_add<<<NB_SCAN, 256>>>();
    scatter_kernel<<<(NE + 255) / 256, 256>>>(src, dst);
    embed_kernel<<<(NN * 32 + 255) / 256, 256>>>(x, emb);

    // E = edge_attr @ Wecat -> bf16 [NE, 768] (lane-interleaved f/s layout)
    {
        dim3 grid(NE / 64, 12);
        gemm_tf32<32, 1><<<grid, 256, SMEM_E>>>(ea, (const float*)p_Wecat, nullptr, p_E, 768, 768);
    }

    float* hbufs[3] = {(float*)p_h0, (float*)p_h1, (float*)p_h0};
    for (int l = 0; l < 3; ++l) {
        dim3 grid(NPAD / 64, 8);
        gemm_tf32<128, 0><<<grid, 256, SMEM_NODE>>>(
            hbufs[l], (const float*)p_Wcat + l * 65536,
            (const float*)p_bcat + l * 512, p_G, 512, 512);
        edge_kernel<<<(NN + 7) / 8, 256>>>(l);
    }

    pool_kernel<<<512, 128>>>((const float*)p_h1, batch);
    final_kernel<<<NG, 128>>>(Wlin, blin, out);
}

// round 9
// speedup vs baseline: 1.3591x; 1.3001x over previous
#include <cuda_runtime.h>
#include <cuda_bf16.h>
#include <mma.h>

using namespace nvcuda;

#define NN 50000
#define NPAD 50048            // multiple of 64
#define NE 800000             // divisible by 64
#define NG 500
#define HD 128
#define NB_SCAN 196           // ceil(50000/256)

// ---------------- static device scratch (allocation-free rule) ----------------
__device__ float d_h0[(size_t)NPAD * 128];
__device__ float d_h1[(size_t)NPAD * 128];
__device__ float d_G[(size_t)NPAD * 512];                  // [Af|Bf|As|Bs] per node
__device__ __nv_bfloat16 d_E[(size_t)NE * 768];            // CSR-ordered, 3 layers x 256, lane-interleaved f/s
__device__ int d_cnt[NN];
__device__ int d_off[NN + 1];
__device__ int d_cur[NN];
__device__ int d_csr_src[NE];
__device__ int d_csr_eid[NE];
__device__ int d_bsum[256];
__device__ float d_pool[NG * HD];
__device__ float d_cntf[NG];
__device__ float d_Wcat[3 * 128 * 512];
__device__ float d_bcat[3 * 512];
__device__ __nv_bfloat16 d_Wecat_h[32 * 768];

// ---------------- fast math ----------------
__device__ __forceinline__ float ex2f(float x) { float r; asm("ex2.approx.f32 %0, %1;" : "=f"(r) : "f"(x)); return r; }
__device__ __forceinline__ float lg2f(float x) { float r; asm("lg2.approx.f32 %0, %1;" : "=f"(r) : "f"(x)); return r; }
__device__ __forceinline__ float tanhf_(float x){ float r; asm("tanh.approx.f32 %0, %1;" : "=f"(r) : "f"(x)); return r; }
__device__ __forceinline__ float tf32r(float x) { float r; asm("cvt.rna.tf32.f32 %0, %1;" : "=f"(r) : "f"(x)); return r; }

#define LOG2E 1.4426950408889634f
#define LN2   0.6931471805599453f

__device__ __forceinline__ float msgf(float pf, float ps) {
    float sg = fmaf(0.5f, tanhf_(0.5f * pf), 0.5f);          // sigmoid, 1 MUFU
    float sp = LN2 * lg2f(1.0f + ex2f(ps * LOG2E));          // softplus, 2 MUFU
    sp = (ps > 15.0f) ? ps : sp;
    return sg * sp;
}

__device__ __forceinline__ void accum4(float4& acc, const float4& af, const float4& as4,
                                       const float4& bf4, const float4& bs4, const uint4& q) {
    float2 ef0 = __bfloat1622float2(*(const __nv_bfloat162*)&q.x);
    float2 ef1 = __bfloat1622float2(*(const __nv_bfloat162*)&q.y);
    float2 es0 = __bfloat1622float2(*(const __nv_bfloat162*)&q.z);
    float2 es1 = __bfloat1622float2(*(const __nv_bfloat162*)&q.w);
    acc.x += msgf(af.x + bf4.x + ef0.x, as4.x + bs4.x + es0.x);
    acc.y += msgf(af.y + bf4.y + ef0.y, as4.y + bs4.y + es0.y);
    acc.z += msgf(af.z + bf4.z + ef1.x, as4.z + bs4.z + es1.x);
    acc.w += msgf(af.w + bf4.w + ef1.y, as4.w + bs4.w + es1.y);
}

// ---------------- misc kernels ----------------
__global__ void zero_stats() {
    int i = blockIdx.x * blockDim.x + threadIdx.x;
    if (i < NG * HD) d_pool[i] = 0.0f;
    if (i < NG) d_cntf[i] = 0.0f;
    if (i < NN) d_cnt[i] = 0;
}

__global__ void repack_kernel(const float* __restrict__ Wf1, const float* __restrict__ Ws1,
                              const float* __restrict__ Wf2, const float* __restrict__ Ws2,
                              const float* __restrict__ Wf3, const float* __restrict__ Ws3,
                              const float* __restrict__ bf1, const float* __restrict__ bs1,
                              const float* __restrict__ bf2, const float* __restrict__ bs2,
                              const float* __restrict__ bf3, const float* __restrict__ bs3) {
    int idx = blockIdx.x * blockDim.x + threadIdx.x;
    const float* Wf[3] = {Wf1, Wf2, Wf3};
    const float* Ws[3] = {Ws1, Ws2, Ws3};
    if (idx < 3 * 128 * 512) {
        int l = idx / 65536;
        int rem = idx - l * 65536;
        int k = rem >> 9;
        int c = rem & 511;
        int g = c >> 7;            // 0 Af, 1 Bf, 2 As, 3 Bs
        int c0 = c & 127;
        float v;
        if (g == 0)      v = Wf[l][k * 128 + c0];
        else if (g == 1) v = Wf[l][(128 + k) * 128 + c0];
        else if (g == 2) v = Ws[l][k * 128 + c0];
        else             v = Ws[l][(128 + k) * 128 + c0];
        d_Wcat[idx] = v;
        return;
    }
    int idx2 = idx - 3 * 128 * 512;
    if (idx2 < 32 * 768) {
        // lane-interleaved: within each layer's 256 cols,
        // cols 8*li..8*li+3 = f channels 4li..4li+3; 8*li+4..8*li+7 = s channels 4li..4li+3
        int r = idx2 / 768;
        int c = idx2 - r * 768;
        int l = c >> 8;            // layer
        int w = c & 255;
        int li = w >> 3;           // lane
        int q = w & 7;
        int g = q >> 2;            // 0 f, 1 s
        int c0 = 4 * li + (q & 3);
        d_Wecat_h[idx2] = __float2bfloat16((g == 0 ? Wf[l] : Ws[l])[(256 + r) * 128 + c0]);
        return;
    }
    int idx3 = idx2 - 32 * 768;
    if (idx3 < 3 * 512) {
        int l = idx3 / 512;
        int c = idx3 - l * 512;
        int g = c >> 7;
        int c0 = c & 127;
        const float* bfp[3] = {bf1, bf2, bf3};
        const float* bsp[3] = {bs1, bs2, bs3};
        float v = (g == 0) ? bfp[l][c0] : ((g == 2) ? bsp[l][c0] : 0.0f);
        d_bcat[idx3] = v;
    }
}

__global__ void count_kernel(const int* __restrict__ dst) {
    int e = blockIdx.x * blockDim.x + threadIdx.x;
    if (e < NE) atomicAdd(&d_cnt[dst[e]], 1);
}

// ---- hierarchical scan ----
__device__ __forceinline__ int block_scan_incl(int v, int* wsum, int lane, int wid) {
    int x = v;
    #pragma unroll
    for (int o = 1; o < 32; o <<= 1) {
        int t = __shfl_up_sync(0xffffffffu, x, o);
        if (lane >= o) x += t;
    }
    if (lane == 31) wsum[wid] = x;
    __syncthreads();
    if (wid == 0) {
        int t2 = (lane < 8) ? wsum[lane] : 0;
        #pragma unroll
        for (int o = 1; o < 8; o <<= 1) {
            int t = __shfl_up_sync(0xffffffffu, t2, o);
            if (lane >= o) t2 += t;
        }
        if (lane < 8) wsum[lane] = t2;
    }
    __syncthreads();
    return x + (wid ? wsum[wid - 1] : 0);
}

__global__ void scan_blocks() {
    __shared__ int wsum[8];
    int lane = threadIdx.x & 31, wid = threadIdx.x >> 5;
    int i = blockIdx.x * 256 + threadIdx.x;
    int v = (i < NN) ? d_cnt[i] : 0;
    int incl = block_scan_incl(v, wsum, lane, wid);
    if (i < NN) d_off[i] = incl - v;
    if (threadIdx.x == 255) d_bsum[blockIdx.x] = incl;
}

__global__ void scan_top() {
    __shared__ int wsum[8];
    int lane = threadIdx.x & 31, wid = threadIdx.x >> 5;
    int t = threadIdx.x;
    int v = (t < NB_SCAN) ? d_bsum[t] : 0;
    int incl = block_scan_incl(v, wsum, lane, wid);
    if (t < NB_SCAN) d_bsum[t] = incl - v;
}

__global__ void scan_add() {
    int i = blockIdx.x * 256 + threadIdx.x;
    if (i < NN) {
        int o = d_off[i] + d_bsum[blockIdx.x];
        d_off[i] = o;
        d_cur[i] = o;
    }
    if (i == 0) d_off[NN] = NE;
}

__global__ void scatter_kernel(const int* __restrict__ src, const int* __restrict__ dst) {
    int e = blockIdx.x * blockDim.x + threadIdx.x;
    if (e < NE) {
        int d = dst[e];
        int p = atomicAdd(&d_cur[d], 1);
        d_csr_src[p] = src[e];
        d_csr_eid[p] = e;
    }
}

__global__ void embed_kernel(const int* __restrict__ x, const float* __restrict__ emb) {
    int idx = blockIdx.x * blockDim.x + threadIdx.x;
    if (idx >= NN * 32) return;
    int n = idx >> 5, c4 = idx & 31;
    float4 v = ((const float4*)(emb + (size_t)x[n] * 128))[c4];
    ((float4*)(d_h0 + (size_t)n * 128))[c4] = v;
}

// ---------------- E-GEMM: bf16 wmma, one block per 64 CSR rows, all 768 cols in-block ----------------
// smem layout (bytes): Bs bf16[32][784] = 50176 | As bf16[64][40] = 5120 | Us f32[64][68] = 17408 | eids int[64] = 256
#define EG_SMEM (50176 + 5120 + 17408 + 256)
__global__ void __launch_bounds__(256) egemm_kernel(const float* __restrict__ ea) {
    extern __shared__ char smraw[];
    __nv_bfloat16 (*Bs)[784] = (__nv_bfloat16 (*)[784])smraw;
    __nv_bfloat16 (*As)[40]  = (__nv_bfloat16 (*)[40])(smraw + 50176);
    float (*Us)[68]          = (float (*)[68])(smraw + 50176 + 5120);
    int* eids                = (int*)(smraw + 50176 + 5120 + 17408);

    int tid = threadIdx.x;
    size_t rowBase = (size_t)blockIdx.x * 64;

    if (tid < 64) eids[tid] = d_csr_eid[rowBase + tid];
    // load full B panel 32x768 bf16 (96 uint4 per row)
    for (int i = tid; i < 3072; i += 256) {
        int r = i / 96, c8 = (i - r * 96) * 8;
        *(uint4*)&Bs[r][c8] = *(const uint4*)&d_Wecat_h[r * 768 + c8];
    }
    __syncthreads();
    // gather A rows (32 floats each) via eid, convert to bf16
    for (int i = tid; i < 512; i += 256) {
        int r = i >> 3, c4 = (i & 7) * 4;
        float4 v = *(const float4*)(ea + (size_t)eids[r] * 32 + c4);
        *(__nv_bfloat162*)&As[r][c4]     = __float22bfloat162_rn(make_float2(v.x, v.y));
        *(__nv_bfloat162*)&As[r][c4 + 2] = __float22bfloat162_rn(make_float2(v.z, v.w));
    }
    __syncthreads();

    int warp = tid >> 5;
    int wm = warp >> 2, wn = warp & 3;

    for (int chunk = 0; chunk < 12; ++chunk) {
        wmma::fragment<wmma::accumulator, 16, 16, 16, float> c0, c1;
        wmma::fill_fragment(c0, 0.0f);
        wmma::fill_fragment(c1, 0.0f);
        #pragma unroll
        for (int k0 = 0; k0 < 32; k0 += 16) {
            wmma::fragment<wmma::matrix_a, 16, 16, 16, __nv_bfloat16, wmma::row_major> a0, a1;
            wmma::fragment<wmma::matrix_b, 16, 16, 16, __nv_bfloat16, wmma::row_major> b;
            wmma::load_matrix_sync(a0, &As[wm * 32][k0], 40);
            wmma::load_matrix_sync(a1, &As[wm * 32 + 16][k0], 40);
            wmma::load_matrix_sync(b, &Bs[k0][chunk * 64 + wn * 16], 784);
            wmma::mma_sync(c0, a0, b, c0);
            wmma::mma_sync(c1, a1, b, c1);
        }
        wmma::store_matrix_sync(&Us[wm * 32][wn * 16], c0, 68, wmma::mem_row_major);
        wmma::store_matrix_sync(&Us[wm * 32 + 16][wn * 16], c1, 68, wmma::mem_row_major);
        __syncthreads();
        for (int i = tid; i < 512; i += 256) {
            int r = i >> 3, c = (i & 7) << 3;
            float4 v0 = *(const float4*)&Us[r][c];
            float4 v1 = *(const float4*)&Us[r][c + 4];
            __nv_bfloat162 p0 = __float22bfloat162_rn(make_float2(v0.x, v0.y));
            __nv_bfloat162 p1 = __float22bfloat162_rn(make_float2(v0.z, v0.w));
            __nv_bfloat162 p2 = __float22bfloat162_rn(make_float2(v1.x, v1.y));
            __nv_bfloat162 p3 = __float22bfloat162_rn(make_float2(v1.z, v1.w));
            uint4 pk;
            pk.x = *(unsigned*)&p0; pk.y = *(unsigned*)&p1;
            pk.z = *(unsigned*)&p2; pk.w = *(unsigned*)&p3;
            *(uint4*)&d_E[(rowBase + r) * 768 + chunk * 64 + c] = pk;
        }
        __syncthreads();
    }
}

// ---------------- node GEMM: tf32 wmma ----------------
template <int K>
__global__ void __launch_bounds__(256)
gemm_tf32(const float* __restrict__ A, const float* __restrict__ B,
          const float* __restrict__ bias, float* __restrict__ C,
          int ldb, int ldc) {
    extern __shared__ float sm[];
    float (*As)[K + 4] = (float (*)[K + 4])sm;
    float (*Bs)[68]    = (float (*)[68])(sm + 64 * (K + 4));
    float (*Us)[68]    = (float (*)[68])(sm + 64 * (K + 4) + K * 68);

    int tid = threadIdx.x;
    size_t rowBase = (size_t)blockIdx.x * 64;
    int colBase = blockIdx.y * 64;

    constexpr int K4 = K / 4;
    for (int i = tid; i < 64 * K4; i += 256) {
        int r = i / K4, c = (i - r * K4) * 4;
        float4 v = *(const float4*)&A[(rowBase + r) * K + c];
        v.x = tf32r(v.x); v.y = tf32r(v.y); v.z = tf32r(v.z); v.w = tf32r(v.w);
        *(float4*)&As[r][c] = v;
    }
    for (int i = tid; i < K * 16; i += 256) {
        int r = i / 16, c = (i - r * 16) * 4;
        float4 v = *(const float4*)&B[(size_t)r * ldb + colBase + c];
        v.x = tf32r(v.x); v.y = tf32r(v.y); v.z = tf32r(v.z); v.w = tf32r(v.w);
        *(float4*)&Bs[r][c] = v;
    }
    __syncthreads();

    int warp = tid >> 5;
    int wm = warp >> 2, wn = warp & 3;

    wmma::fragment<wmma::accumulator, 16, 16, 8, float> c0, c1;
    wmma::fill_fragment(c0, 0.0f);
    wmma::fill_fragment(c1, 0.0f);

    #pragma unroll
    for (int k0 = 0; k0 < K; k0 += 8) {
        wmma::fragment<wmma::matrix_a, 16, 16, 8, wmma::precision::tf32, wmma::row_major> a0, a1;
        wmma::fragment<wmma::matrix_b, 16, 16, 8, wmma::precision::tf32, wmma::row_major> b;
        wmma::load_matrix_sync(a0, &As[wm * 32][k0], K + 4);
        wmma::load_matrix_sync(a1, &As[wm * 32 + 16][k0], K + 4);
        wmma::load_matrix_sync(b, &Bs[k0][wn * 16], 68);
        wmma::mma_sync(c0, a0, b, c0);
        wmma::mma_sync(c1, a1, b, c1);
    }
    wmma::store_matrix_sync(&Us[wm * 32][wn * 16], c0, 68, wmma::mem_row_major);
    wmma::store_matrix_sync(&Us[wm * 32 + 16][wn * 16], c1, 68, wmma::mem_row_major);
    __syncthreads();

    for (int i = tid; i < 1024; i += 256) {
        int r = i >> 4, c = (i & 15) << 2;
        float4 v = *(const float4*)&Us[r][c];
        float4 b4 = *(const float4*)&bias[colBase + c];
        v.x += b4.x; v.y += b4.y; v.z += b4.z; v.w += b4.w;
        *(float4*)&C[(rowBase + r) * (size_t)ldc + colBase + c] = v;
    }
}

// ---------------- edge kernel: warp per dst node, sequential E, unroll 4 ----------------
__global__ void __launch_bounds__(256) edge_kernel(int layer) {
    int n = blockIdx.x * 8 + (threadIdx.x >> 5);
    if (n >= NN) return;
    int l = threadIdx.x & 31;
    const float* hin  = (layer == 1) ? d_h1 : d_h0;
    float*       hout = (layer == 1) ? d_h0 : d_h1;

    const float4* Gn = (const float4*)(d_G + (size_t)n * 512);
    float4 af  = Gn[l];
    float4 as4 = Gn[64 + l];
    float4 acc = make_float4(0.f, 0.f, 0.f, 0.f);

    int beg = d_off[n], end = d_off[n + 1];
    const __nv_bfloat16* Eb = d_E + (size_t)layer * 256 + 8 * l;   // + p*768

    int p = beg;
    for (; p + 4 <= end; p += 4) {
        int s0 = d_csr_src[p];
        int s1 = d_csr_src[p + 1];
        int s2 = d_csr_src[p + 2];
        int s3 = d_csr_src[p + 3];
        uint4 q0 = *(const uint4*)(Eb + (size_t)p * 768);
        uint4 q1 = *(const uint4*)(Eb + (size_t)(p + 1) * 768);
        uint4 q2 = *(const uint4*)(Eb + (size_t)(p + 2) * 768);
        uint4 q3 = *(const uint4*)(Eb + (size_t)(p + 3) * 768);
        const float4* G0 = (const float4*)(d_G + (size_t)s0 * 512);
        const float4* G1 = (const float4*)(d_G + (size_t)s1 * 512);
        const float4* G2 = (const float4*)(d_G + (size_t)s2 * 512);
        const float4* G3 = (const float4*)(d_G + (size_t)s3 * 512);
        float4 F0 = G0[32 + l], S0 = G0[96 + l];
        float4 F1 = G1[32 + l], S1 = G1[96 + l];
        float4 F2 = G2[32 + l], S2 = G2[96 + l];
        float4 F3 = G3[32 + l], S3 = G3[96 + l];
        accum4(acc, af, as4, F0, S0, q0);
        accum4(acc, af, as4, F1, S1, q1);
        accum4(acc, af, as4, F2, S2, q2);
        accum4(acc, af, as4, F3, S3, q3);
    }
    for (; p < end; ++p) {
        int s0 = d_csr_src[p];
        uint4 q0 = *(const uint4*)(Eb + (size_t)p * 768);
        const float4* G0 = (const float4*)(d_G + (size_t)s0 * 512);
        float4 F0 = G0[32 + l], S0 = G0[96 + l];
        accum4(acc, af, as4, F0, S0, q0);
    }
    float4 h = ((const float4*)(hin + (size_t)n * 128))[l];
    h.x = fmaxf(h.x + acc.x, 0.f);
    h.y = fmaxf(h.y + acc.y, 0.f);
    h.z = fmaxf(h.z + acc.z, 0.f);
    h.w = fmaxf(h.w + acc.w, 0.f);
    ((float4*)(hout + (size_t)n * 128))[l] = h;
}

// ---------------- pooling ----------------
__global__ void pool_kernel(const float* __restrict__ h, const int* __restrict__ batch) {
    int t = threadIdx.x;
    int per = (NN + gridDim.x - 1) / gridDim.x;
    int n0 = blockIdx.x * per;
    int n1 = n0 + per; if (n1 > NN) n1 = NN;
    if (n0 >= n1) return;
    int g = batch[n0];
    float acc = 0.f, cnt = 0.f;
    for (int n = n0; n < n1; ++n) {
        int gn = batch[n];
        if (gn != g) {
            atomicAdd(&d_pool[g * 128 + t], acc);
            if (t == 0) atomicAdd(&d_cntf[g], cnt);
            acc = 0.f; cnt = 0.f; g = gn;
        }
        acc += h[(size_t)n * 128 + t];
        cnt += 1.f;
    }
    atomicAdd(&d_pool[g * 128 + t], acc);
    if (t == 0) atomicAdd(&d_cntf[g], cnt);
}

__global__ void final_kernel(const float* __restrict__ Wlin, const float* __restrict__ blin,
                             float* __restrict__ out) {
    __shared__ float pm[128];
    int gph = blockIdx.x, t = threadIdx.x;
    float inv = 1.0f / fmaxf(d_cntf[gph], 1.0f);
    pm[t] = d_pool[gph * 128 + t] * inv;
    __syncthreads();
    float s = blin[t];
    #pragma unroll 8
    for (int k = 0; k < 128; ++k) s += pm[k] * Wlin[k * 128 + t];
    out[gph * 128 + t] = s;
}

// ---------------- host ----------------
extern "C" void kernel_launch(void* const* d_in, const int* in_sizes, int n_in,
                              void* d_out, int out_size) {
    const int*   x     = (const int*)d_in[0];
    const int*   ei    = (const int*)d_in[1];
    const float* ea    = (const float*)d_in[2];
    const int*   batch = (const int*)d_in[3];
    const float* emb   = (const float*)d_in[4];
    const float* Wf1 = (const float*)d_in[5],  *bf1 = (const float*)d_in[6];
    const float* Ws1 = (const float*)d_in[7],  *bs1 = (const float*)d_in[8];
    const float* Wf2 = (const float*)d_in[9],  *bf2 = (const float*)d_in[10];
    const float* Ws2 = (const float*)d_in[11], *bs2 = (const float*)d_in[12];
    const float* Wf3 = (const float*)d_in[13], *bf3 = (const float*)d_in[14];
    const float* Ws3 = (const float*)d_in[15], *bs3 = (const float*)d_in[16];
    const float* Wlin = (const float*)d_in[17], *blin = (const float*)d_in[18];
    float* out = (float*)d_out;

    const int* src = ei;
    const int* dst = ei + NE;

    const int SMEM_NODE = (64 * 132 + 128 * 68 + 64 * 68) * 4;  // 86016
    cudaFuncSetAttribute(gemm_tf32<128>, cudaFuncAttributeMaxDynamicSharedMemorySize, SMEM_NODE);
    cudaFuncSetAttribute(egemm_kernel, cudaFuncAttributeMaxDynamicSharedMemorySize, EG_SMEM);

    void *p_h0, *p_h1, *p_G, *p_Wcat, *p_bcat;
    cudaGetSymbolAddress(&p_h0, d_h0);
    cudaGetSymbolAddress(&p_h1, d_h1);
    cudaGetSymbolAddress(&p_G, d_G);
    cudaGetSymbolAddress(&p_Wcat, d_Wcat);
    cudaGetSymbolAddress(&p_bcat, d_bcat);

    zero_stats<<<250, 256>>>();
    repack_kernel<<<(3 * 128 * 512 + 32 * 768 + 3 * 512 + 255) / 256, 256>>>(
        Wf1, Ws1, Wf2, Ws2, Wf3, Ws3, bf1, bs1, bf2, bs2, bf3, bs3);
    count_kernel<<<(NE + 255) / 256, 256>>>(dst);
    scan_blocks<<<NB_SCAN, 256>>>();
    scan_top<<<1, 256>>>();
    scan_add<<<NB_SCAN, 256>>>();
    scatter_kernel<<<(NE + 255) / 256, 256>>>(src, dst);
    embed_kernel<<<(NN * 32 + 255) / 256, 256>>>(x, emb);

    // E = edge_attr[eid[p]] @ Wecat -> bf16 [NE(csr order), 768]
    egemm_kernel<<<NE / 64, 256, EG_SMEM>>>(ea);

    float* hbufs[3] = {(float*)p_h0, (float*)p_h1, (float*)p_h0};
    for (int l = 0; l < 3; ++l) {
        dim3 grid(NPAD / 64, 8);
        gemm_tf32<128><<<grid, 256, SMEM_NODE>>>(
            hbufs[l], (const float*)p_Wcat + l * 65536,
            (const float*)p_bcat + l * 512, (float*)p_G, 512, 512);
        edge_kernel<<<(NN + 7) / 8, 256>>>(l);
    }

    pool_kernel<<<512, 128>>>((const float*)p_h1, batch);
    final_kernel<<<NG, 128>>>(Wlin, blin, out);
}